// round 16
// baseline (speedup 1.0000x reference)
#include <cuda_runtime.h>
#include <cuda_fp16.h>
#include <cstdint>
#include <math.h>

// ---------------------------------------------------------------------------
// Problem constants
// ---------------------------------------------------------------------------
#define M_ROWS 16384
#define N_COLS 1000
#define N_PAD  1024
#define K_DIM  4096
#define NUM_TTA_ 64
#define KEPT 6
#define NBATCH 256

// GEMM tiling (best measured): 128x128 CTA tile, 8 warps (4m x 2n),
// warp tile 32x64, BKH=32 (64B rows, SW64), 3-stage pipeline, 2 CTAs/SM.
#define BM 128
#define BN 128
#define BKH 32
#define KITERS (K_DIM / BKH)   // 128
#define NSTAGE 3
#define ARR_BYTES 8192         // 128 rows x 64 B
#define STG_BYTES (4 * ARR_BYTES)   // Ahi|Alo|Bhi|Blo = 32 KB

// ---------------------------------------------------------------------------
// Device-global scratch
// ---------------------------------------------------------------------------
__device__ __half g_xh[(size_t)M_ROWS * K_DIM];
__device__ __half g_xl[(size_t)M_ROWS * K_DIM];
__device__ __half g_wh[(size_t)N_PAD * K_DIM];
__device__ __half g_wl[(size_t)N_PAD * K_DIM];
// packed per-(row, 64-col block) partials: {max, S, T, bitcast(argmax)}
__device__ float4 g_part[(size_t)M_ROWS * 16];

// ---------------------------------------------------------------------------
// PTX helpers
// ---------------------------------------------------------------------------
__device__ __forceinline__ uint32_t smem_u32(const void* p) {
    uint32_t a;
    asm("{ .reg .u64 t; cvta.to.shared.u64 t, %1; cvt.u32.u64 %0, t; }"
        : "=r"(a) : "l"(p));
    return a;
}

#define SWZ64(o) ((o) ^ (((o) >> 3) & 0x30))

__device__ __forceinline__ void cp16(uint32_t saddr, const void* g) {
    asm volatile("cp.async.cg.shared.global [%0], [%1], 16;"
                 :: "r"(saddr), "l"(g) : "memory");
}

#define LDSM4(R, ADDR) \
    asm volatile("ldmatrix.sync.aligned.m8n8.x4.shared.b16 {%0,%1,%2,%3}, [%4];" \
        : "=r"((R)[0]), "=r"((R)[1]), "=r"((R)[2]), "=r"((R)[3]) : "r"(ADDR))

__device__ __forceinline__ void mma16816(float* c, const uint32_t* a,
                                         uint32_t b0, uint32_t b1) {
    asm volatile(
        "mma.sync.aligned.m16n8k16.row.col.f32.f16.f16.f32 "
        "{%0,%1,%2,%3}, {%4,%5,%6,%7}, {%8,%9}, {%0,%1,%2,%3};"
        : "+f"(c[0]), "+f"(c[1]), "+f"(c[2]), "+f"(c[3])
        : "r"(a[0]), "r"(a[1]), "r"(a[2]), "r"(a[3]), "r"(b0), "r"(b1));
}

// ---------------------------------------------------------------------------
// Pre-pass 1: split x (fp32) -> fp16 hi + fp16 lo residual
// ---------------------------------------------------------------------------
__global__ __launch_bounds__(256)
void split_x_kernel(const float* __restrict__ x) {
    size_t i = ((size_t)blockIdx.x * 256 + threadIdx.x) * 8;
    float4 v0 = *(const float4*)(x + i);
    float4 v1 = *(const float4*)(x + i + 4);
    float f[8] = {v0.x, v0.y, v0.z, v0.w, v1.x, v1.y, v1.z, v1.w};
    __half h[8], l[8];
#pragma unroll
    for (int e = 0; e < 8; e++) {
        h[e] = __float2half_rn(f[e]);
        l[e] = __float2half_rn(f[e] - __half2float(h[e]));
    }
    *(uint4*)(g_xh + i) = *(const uint4*)h;
    *(uint4*)(g_xl + i) = *(const uint4*)l;
}

// ---------------------------------------------------------------------------
// Pre-pass 2: transpose W [K, N] -> [N_PAD, K], split fp16 hi + lo
// ---------------------------------------------------------------------------
__global__ __launch_bounds__(1024)
void split_wt_kernel(const float* __restrict__ W) {
    __shared__ float tile[32][33];
    const int k0 = blockIdx.x * 32;
    const int n0 = blockIdx.y * 32;
    const int tx = threadIdx.x, ty = threadIdx.y;
    const int n = n0 + tx;
    float v = (n < N_COLS) ? W[(size_t)(k0 + ty) * N_COLS + n] : 0.0f;
    tile[ty][tx] = v;
    __syncthreads();
    float u = tile[tx][ty];
    __half h = __float2half_rn(u);
    __half l = __float2half_rn(u - __half2float(h));
    size_t o = (size_t)(n0 + ty) * K_DIM + k0 + tx;
    g_wh[o] = h;
    g_wl[o] = l;
}

// ---------------------------------------------------------------------------
// Kernel A: fp16x2 split GEMM + fused softmax/argmax partials (packed f4)
// ---------------------------------------------------------------------------
#define SMEM_BYTES (NSTAGE * STG_BYTES + 1024)

__global__ __launch_bounds__(256, 2)
void gemm_fp16x2_kernel(const float* __restrict__ bias) {
    extern __shared__ char smem_raw[];
    uint32_t sbase = smem_u32(smem_raw);
    uint32_t pad = (256u - (sbase & 255u)) & 255u;
    char* smem_al = smem_raw + pad;
    sbase += pad;
    float* sbias = (float*)(smem_al + NSTAGE * STG_BYTES);

    const int tid  = threadIdx.x;
    const int lane = tid & 31;
    const int wid  = tid >> 5;
    const int wm   = wid & 3;
    const int wn   = wid >> 2;
    const int m0 = blockIdx.y * BM;
    const int n0 = blockIdx.x * BN;

    if (tid < BN) {
        int c = n0 + tid;
        sbias[tid] = (c < N_COLS) ? bias[c] : 0.0f;
    }

    const int c0row = tid >> 2;
    const int c0cb  = (tid & 3) * 16;
    const int c1row = (tid + 256) >> 2;
    const uint32_t sw0 = SWZ64((uint32_t)(c0row * 64 + c0cb));
    const uint32_t sw1 = SWZ64((uint32_t)(c1row * 64 + c0cb));

    const __half* gAh0 = g_xh + (size_t)(m0 + c0row) * K_DIM + (c0cb >> 1);
    const __half* gAl0 = g_xl + (size_t)(m0 + c0row) * K_DIM + (c0cb >> 1);
    const __half* gBh0 = g_wh + (size_t)(n0 + c0row) * K_DIM + (c0cb >> 1);
    const __half* gBl0 = g_wl + (size_t)(n0 + c0row) * K_DIM + (c0cb >> 1);
    const __half* gAh1 = g_xh + (size_t)(m0 + c1row) * K_DIM + (c0cb >> 1);
    const __half* gAl1 = g_xl + (size_t)(m0 + c1row) * K_DIM + (c0cb >> 1);
    const __half* gBh1 = g_wh + (size_t)(n0 + c1row) * K_DIM + (c0cb >> 1);
    const __half* gBl1 = g_wl + (size_t)(n0 + c1row) * K_DIM + (c0cb >> 1);

    float cc[2][8][4];
#pragma unroll
    for (int mt = 0; mt < 2; mt++)
#pragma unroll
        for (int n8 = 0; n8 < 8; n8++)
#pragma unroll
            for (int j = 0; j < 4; j++) cc[mt][n8][j] = 0.f;

#define LOAD_STAGE(SB, KH)                                                     \
    do {                                                                       \
        cp16((SB) + 0 * ARR_BYTES + sw0, gAh0 + (KH));                         \
        cp16((SB) + 0 * ARR_BYTES + sw1, gAh1 + (KH));                         \
        cp16((SB) + 1 * ARR_BYTES + sw0, gAl0 + (KH));                         \
        cp16((SB) + 1 * ARR_BYTES + sw1, gAl1 + (KH));                         \
        cp16((SB) + 2 * ARR_BYTES + sw0, gBh0 + (KH));                         \
        cp16((SB) + 2 * ARR_BYTES + sw1, gBh1 + (KH));                         \
        cp16((SB) + 3 * ARR_BYTES + sw0, gBl0 + (KH));                         \
        cp16((SB) + 3 * ARR_BYTES + sw1, gBl1 + (KH));                         \
        asm volatile("cp.async.commit_group;" ::: "memory");                   \
    } while (0)

    LOAD_STAGE(sbase, 0);
    LOAD_STAGE(sbase + STG_BYTES, BKH);

    for (int it = 0; it < KITERS; it++) {
        if (it < KITERS - 1) {
            asm volatile("cp.async.wait_group 1;" ::: "memory");
        } else {
            asm volatile("cp.async.wait_group 0;" ::: "memory");
        }
        __syncthreads();

        if (it + 2 < KITERS) {
            const uint32_t sb = sbase + ((it + 2) % NSTAGE) * STG_BYTES;
            LOAD_STAGE(sb, (it + 2) * BKH);
        }

        const uint32_t sA  = sbase + (it % NSTAGE) * STG_BYTES;
        const uint32_t sAl = sA + 1 * ARR_BYTES;
        const uint32_t sB  = sA + 2 * ARR_BYTES;
        const uint32_t sBl = sA + 3 * ARR_BYTES;

#pragma unroll
        for (int ks = 0; ks < 2; ks++) {
            const uint32_t chunkb = ks * 32 + ((lane >> 4) << 4);
            uint32_t ah[2][4], al[2][4];
#pragma unroll
            for (int mt = 0; mt < 2; mt++) {
                uint32_t off = SWZ64((uint32_t)((wm * 32 + mt * 16 + (lane & 15)) * 64) + chunkb);
                LDSM4(ah[mt], sA + off);
                LDSM4(al[mt], sAl + off);
            }
#pragma unroll
            for (int nt = 0; nt < 4; nt++) {
                uint32_t off = SWZ64((uint32_t)((wn * 64 + nt * 16 + (lane & 15)) * 64) + chunkb);
                uint32_t bh[4], bl[4];
                LDSM4(bh, sB + off);
                LDSM4(bl, sBl + off);
#pragma unroll
                for (int mt = 0; mt < 2; mt++) {
#pragma unroll
                    for (int h2 = 0; h2 < 2; h2++) {
                        const int n8 = nt * 2 + h2;
                        mma16816(cc[mt][n8], ah[mt], bh[h2], bh[h2 + 2]);
                        mma16816(cc[mt][n8], ah[mt], bl[h2], bl[h2 + 2]);
                        mma16816(cc[mt][n8], al[mt], bh[h2], bh[h2 + 2]);
                    }
                }
            }
        }
    }

    // ---- fused epilogue: per-(row, 64-col block) partials, packed float4 ----
    const int nblk = blockIdx.x * 2 + wn;   // 0..15, ascending col order
#pragma unroll
    for (int mt = 0; mt < 2; mt++) {
#pragma unroll
        for (int hf = 0; hf < 2; hf++) {
            const int row = m0 + wm * 32 + mt * 16 + (lane >> 2) + hf * 8;

            float mx = -3.4e38f;
            int am = 0;
#pragma unroll
            for (int n8 = 0; n8 < 8; n8++) {
                const int sc = wn * 64 + n8 * 8 + (lane & 3) * 2;
                const int c = n0 + sc;
                float v0 = cc[mt][n8][hf * 2 + 0] + sbias[sc];
                float v1 = cc[mt][n8][hf * 2 + 1] + sbias[sc + 1];
                if (c < N_COLS && v0 > mx) { mx = v0; am = c; }
                if (c + 1 < N_COLS && v1 > mx) { mx = v1; am = c + 1; }
            }
#pragma unroll
            for (int s = 1; s <= 2; s <<= 1) {
                float om = __shfl_xor_sync(0xffffffffu, mx, s);
                int oa = __shfl_xor_sync(0xffffffffu, am, s);
                if (om > mx || (om == mx && oa < am)) { mx = om; am = oa; }
            }

            float S = 0.f, T = 0.f;
#pragma unroll
            for (int n8 = 0; n8 < 8; n8++) {
                const int sc = wn * 64 + n8 * 8 + (lane & 3) * 2;
                const int c = n0 + sc;
                if (c < N_COLS) {
                    float u = cc[mt][n8][hf * 2 + 0] + sbias[sc] - mx;
                    float e = expf(u); S += e; T += u * e;
                }
                if (c + 1 < N_COLS) {
                    float u = cc[mt][n8][hf * 2 + 1] + sbias[sc + 1] - mx;
                    float e = expf(u); S += e; T += u * e;
                }
            }
#pragma unroll
            for (int s = 1; s <= 2; s <<= 1) {
                S += __shfl_xor_sync(0xffffffffu, S, s);
                T += __shfl_xor_sync(0xffffffffu, T, s);
            }

            if ((lane & 3) == 0) {
                float4 q;
                q.x = mx; q.y = S; q.z = T; q.w = __int_as_float(am);
                g_part[(size_t)row * 16 + nblk] = q;
            }
        }
    }
}

// ---------------------------------------------------------------------------
// Kernel B: fused merge + vote. One block per batch of 64 rows.
//   4 threads/row merge 16 packed partials (coalesced float4 loads),
//   then the block runs the ranking + O(1) tie-augmented count.
// ---------------------------------------------------------------------------
__global__ __launch_bounds__(256)
void vote_kernel(float* __restrict__ out) {
    __shared__ float ent_s[NUM_TTA_];
    __shared__ int votes_s[NUM_TTA_];
    __shared__ int sv[NUM_TTA_];
    __shared__ int counts[N_COLS];

    const int b = blockIdx.x;
    const int tid = threadIdx.x;

    // --- merge phase: row r = tid>>2, partial quarter = tid&3 ---
    {
        const int rl = tid >> 2;
        const int q4 = (tid & 3) * 4;
        const int row = b * NUM_TTA_ + rl;
        float4 p[4];
#pragma unroll
        for (int j = 0; j < 4; j++)
            p[j] = g_part[(size_t)row * 16 + q4 + j];

        // local (m, am): ascending j => ascending col, strict > keeps first
        float m = p[0].x;
        int am = __float_as_int(p[0].w);
#pragma unroll
        for (int j = 1; j < 4; j++) {
            if (p[j].x > m) { m = p[j].x; am = __float_as_int(p[j].w); }
        }
#pragma unroll
        for (int s = 1; s <= 2; s <<= 1) {
            float om = __shfl_xor_sync(0xffffffffu, m, s);
            int oa = __shfl_xor_sync(0xffffffffu, am, s);
            if (om > m || (om == m && oa < am)) { m = om; am = oa; }
        }
        float S = 0.f, T = 0.f;
#pragma unroll
        for (int j = 0; j < 4; j++) {
            float d = p[j].x - m;
            float e = expf(d);
            S += p[j].y * e;
            T += (p[j].z + d * p[j].y) * e;
        }
#pragma unroll
        for (int s = 1; s <= 2; s <<= 1) {
            S += __shfl_xor_sync(0xffffffffu, S, s);
            T += __shfl_xor_sync(0xffffffffu, T, s);
        }
        if ((tid & 3) == 0) {
            ent_s[rl] = logf(S) - T / S;
            votes_s[rl] = am;
        }
    }
    for (int c = tid; c < N_COLS; c += 256) counts[c] = 0;
    __syncthreads();

    // --- ranking phase ---
    if (tid < NUM_TTA_) {
        float e = ent_s[tid];
        int r = 0;
#pragma unroll
        for (int j = 0; j < NUM_TTA_; j++) {
            float ej = ent_s[j];
            r += (ej < e) || (ej == e && j < tid);
        }
        sv[r] = votes_s[tid];
    }
    __syncthreads();

    // --- counting phase ---
    if (tid == 0) {
        for (int i = 0; i < KEPT; i++) counts[sv[i]]++;
        int mx = 0, nmax = 0;
        for (int i = 0; i < KEPT; i++) {
            int c = sv[i];
            bool first = true;
            for (int j = 0; j < i; j++) if (sv[j] == c) { first = false; break; }
            if (first) {
                int cv = counts[c];
                if (cv > mx) { mx = cv; nmax = 1; }
                else if (cv == mx) nmax++;
            }
        }
        for (int i = 0; i < NUM_TTA_ - KEPT; i++) {
            if (nmax > 1) {
                int c = sv[KEPT + i];
                int nc = counts[c] + 1;
                counts[c] = nc;
                if (nc > mx) { mx = nc; nmax = 1; }
                else if (nc == mx) nmax++;
            }
        }
    }
    __syncthreads();

    for (int c = tid; c < N_COLS; c += 256) {
        out[(size_t)b * N_COLS + c] = logf((float)counts[c] * (1.0f / 64.0f) + 1e-8f);
    }
}

// ---------------------------------------------------------------------------
extern "C" void kernel_launch(void* const* d_in, const int* in_sizes, int n_in,
                              void* d_out, int out_size) {
    const float* x = (const float*)d_in[0];
    const float* W = (const float*)d_in[1];
    const float* b = (const float*)d_in[2];
    float* out = (float*)d_out;

    cudaFuncSetAttribute(gemm_fp16x2_kernel,
                         cudaFuncAttributeMaxDynamicSharedMemorySize, SMEM_BYTES);

    split_x_kernel<<<(M_ROWS * (size_t)K_DIM) / 8 / 256, 256>>>(x);
    split_wt_kernel<<<dim3(K_DIM / 32, N_PAD / 32), dim3(32, 32)>>>(W);

    gemm_fp16x2_kernel<<<dim3(N_PAD / BN, M_ROWS / BM), 256, SMEM_BYTES>>>(b);

    vote_kernel<<<NBATCH, 256>>>(out);
}

// round 17
// speedup vs baseline: 1.0007x; 1.0007x over previous
#include <cuda_runtime.h>
#include <cuda_fp16.h>
#include <cstdint>
#include <math.h>

// ---------------------------------------------------------------------------
// Problem constants
// ---------------------------------------------------------------------------
#define M_ROWS 16384
#define N_COLS 1000
#define N_PAD  1024
#define K_DIM  4096
#define NUM_TTA_ 64
#define KEPT 6
#define NBATCH 256

// GEMM tiling (best measured): 128x128 CTA tile, 8 warps (4m x 2n),
// warp tile 32x64, BKH=32 (64B rows, SW64), 3-stage pipeline, 2 CTAs/SM.
#define BM 128
#define BN 128
#define BKH 32
#define KITERS (K_DIM / BKH)   // 128
#define NSTAGE 3
#define ARR_BYTES 8192         // 128 rows x 64 B
#define STG_BYTES (4 * ARR_BYTES)   // Ahi|Alo|Bhi|Blo = 32 KB

// ---------------------------------------------------------------------------
// Device-global scratch
// ---------------------------------------------------------------------------
__device__ __half g_xh[(size_t)M_ROWS * K_DIM];
__device__ __half g_xl[(size_t)M_ROWS * K_DIM];
__device__ __half g_wh[(size_t)N_PAD * K_DIM];
__device__ __half g_wl[(size_t)N_PAD * K_DIM];
// packed per-(row, 64-col block) partials: {max, S, T, bitcast(argmax)}
__device__ float4 g_part[(size_t)M_ROWS * 16];

// ---------------------------------------------------------------------------
// PTX helpers
// ---------------------------------------------------------------------------
__device__ __forceinline__ uint32_t smem_u32(const void* p) {
    uint32_t a;
    asm("{ .reg .u64 t; cvta.to.shared.u64 t, %1; cvt.u32.u64 %0, t; }"
        : "=r"(a) : "l"(p));
    return a;
}

#define SWZ64(o) ((o) ^ (((o) >> 3) & 0x30))

__device__ __forceinline__ void cp16(uint32_t saddr, const void* g) {
    asm volatile("cp.async.cg.shared.global [%0], [%1], 16;"
                 :: "r"(saddr), "l"(g) : "memory");
}

#define LDSM4(R, ADDR) \
    asm volatile("ldmatrix.sync.aligned.m8n8.x4.shared.b16 {%0,%1,%2,%3}, [%4];" \
        : "=r"((R)[0]), "=r"((R)[1]), "=r"((R)[2]), "=r"((R)[3]) : "r"(ADDR))

__device__ __forceinline__ void mma16816(float* c, const uint32_t* a,
                                         uint32_t b0, uint32_t b1) {
    asm volatile(
        "mma.sync.aligned.m16n8k16.row.col.f32.f16.f16.f32 "
        "{%0,%1,%2,%3}, {%4,%5,%6,%7}, {%8,%9}, {%0,%1,%2,%3};"
        : "+f"(c[0]), "+f"(c[1]), "+f"(c[2]), "+f"(c[3])
        : "r"(a[0]), "r"(a[1]), "r"(a[2]), "r"(a[3]), "r"(b0), "r"(b1));
}

// ---------------------------------------------------------------------------
// Pre-pass 1: split x (fp32) -> fp16 hi + fp16 lo residual
// ---------------------------------------------------------------------------
__global__ __launch_bounds__(256)
void split_x_kernel(const float* __restrict__ x) {
    size_t i = ((size_t)blockIdx.x * 256 + threadIdx.x) * 8;
    float4 v0 = *(const float4*)(x + i);
    float4 v1 = *(const float4*)(x + i + 4);
    float f[8] = {v0.x, v0.y, v0.z, v0.w, v1.x, v1.y, v1.z, v1.w};
    __half h[8], l[8];
#pragma unroll
    for (int e = 0; e < 8; e++) {
        h[e] = __float2half_rn(f[e]);
        l[e] = __float2half_rn(f[e] - __half2float(h[e]));
    }
    *(uint4*)(g_xh + i) = *(const uint4*)h;
    *(uint4*)(g_xl + i) = *(const uint4*)l;
}

// ---------------------------------------------------------------------------
// Pre-pass 2: transpose W [K, N] -> [N_PAD, K], split fp16 hi + lo
// ---------------------------------------------------------------------------
__global__ __launch_bounds__(1024)
void split_wt_kernel(const float* __restrict__ W) {
    __shared__ float tile[32][33];
    const int k0 = blockIdx.x * 32;
    const int n0 = blockIdx.y * 32;
    const int tx = threadIdx.x, ty = threadIdx.y;
    const int n = n0 + tx;
    float v = (n < N_COLS) ? W[(size_t)(k0 + ty) * N_COLS + n] : 0.0f;
    tile[ty][tx] = v;
    __syncthreads();
    float u = tile[tx][ty];
    __half h = __float2half_rn(u);
    __half l = __float2half_rn(u - __half2float(h));
    size_t o = (size_t)(n0 + ty) * K_DIM + k0 + tx;
    g_wh[o] = h;
    g_wl[o] = l;
}

// ---------------------------------------------------------------------------
// Kernel A: fp16x2 split GEMM + fused softmax/argmax partials (packed f4)
// ---------------------------------------------------------------------------
#define SMEM_BYTES (NSTAGE * STG_BYTES + 1024)

__global__ __launch_bounds__(256, 2)
void gemm_fp16x2_kernel(const float* __restrict__ bias) {
    extern __shared__ char smem_raw[];
    uint32_t sbase = smem_u32(smem_raw);
    uint32_t pad = (256u - (sbase & 255u)) & 255u;
    char* smem_al = smem_raw + pad;
    sbase += pad;
    float* sbias = (float*)(smem_al + NSTAGE * STG_BYTES);

    const int tid  = threadIdx.x;
    const int lane = tid & 31;
    const int wid  = tid >> 5;
    const int wm   = wid & 3;
    const int wn   = wid >> 2;
    const int m0 = blockIdx.y * BM;
    const int n0 = blockIdx.x * BN;

    if (tid < BN) {
        int c = n0 + tid;
        sbias[tid] = (c < N_COLS) ? bias[c] : 0.0f;
    }

    const int c0row = tid >> 2;
    const int c0cb  = (tid & 3) * 16;
    const int c1row = (tid + 256) >> 2;
    const uint32_t sw0 = SWZ64((uint32_t)(c0row * 64 + c0cb));
    const uint32_t sw1 = SWZ64((uint32_t)(c1row * 64 + c0cb));

    const __half* gAh0 = g_xh + (size_t)(m0 + c0row) * K_DIM + (c0cb >> 1);
    const __half* gAl0 = g_xl + (size_t)(m0 + c0row) * K_DIM + (c0cb >> 1);
    const __half* gBh0 = g_wh + (size_t)(n0 + c0row) * K_DIM + (c0cb >> 1);
    const __half* gBl0 = g_wl + (size_t)(n0 + c0row) * K_DIM + (c0cb >> 1);
    const __half* gAh1 = g_xh + (size_t)(m0 + c1row) * K_DIM + (c0cb >> 1);
    const __half* gAl1 = g_xl + (size_t)(m0 + c1row) * K_DIM + (c0cb >> 1);
    const __half* gBh1 = g_wh + (size_t)(n0 + c1row) * K_DIM + (c0cb >> 1);
    const __half* gBl1 = g_wl + (size_t)(n0 + c1row) * K_DIM + (c0cb >> 1);

    float cc[2][8][4];
#pragma unroll
    for (int mt = 0; mt < 2; mt++)
#pragma unroll
        for (int n8 = 0; n8 < 8; n8++)
#pragma unroll
            for (int j = 0; j < 4; j++) cc[mt][n8][j] = 0.f;

#define LOAD_STAGE(SB, KH)                                                     \
    do {                                                                       \
        cp16((SB) + 0 * ARR_BYTES + sw0, gAh0 + (KH));                         \
        cp16((SB) + 0 * ARR_BYTES + sw1, gAh1 + (KH));                         \
        cp16((SB) + 1 * ARR_BYTES + sw0, gAl0 + (KH));                         \
        cp16((SB) + 1 * ARR_BYTES + sw1, gAl1 + (KH));                         \
        cp16((SB) + 2 * ARR_BYTES + sw0, gBh0 + (KH));                         \
        cp16((SB) + 2 * ARR_BYTES + sw1, gBh1 + (KH));                         \
        cp16((SB) + 3 * ARR_BYTES + sw0, gBl0 + (KH));                         \
        cp16((SB) + 3 * ARR_BYTES + sw1, gBl1 + (KH));                         \
        asm volatile("cp.async.commit_group;" ::: "memory");                   \
    } while (0)

    LOAD_STAGE(sbase, 0);
    LOAD_STAGE(sbase + STG_BYTES, BKH);

    for (int it = 0; it < KITERS; it++) {
        if (it < KITERS - 1) {
            asm volatile("cp.async.wait_group 1;" ::: "memory");
        } else {
            asm volatile("cp.async.wait_group 0;" ::: "memory");
        }
        __syncthreads();

        if (it + 2 < KITERS) {
            const uint32_t sb = sbase + ((it + 2) % NSTAGE) * STG_BYTES;
            LOAD_STAGE(sb, (it + 2) * BKH);
        }

        const uint32_t sA  = sbase + (it % NSTAGE) * STG_BYTES;
        const uint32_t sAl = sA + 1 * ARR_BYTES;
        const uint32_t sB  = sA + 2 * ARR_BYTES;
        const uint32_t sBl = sA + 3 * ARR_BYTES;

#pragma unroll
        for (int ks = 0; ks < 2; ks++) {
            const uint32_t chunkb = ks * 32 + ((lane >> 4) << 4);
            uint32_t ah[2][4], al[2][4];
#pragma unroll
            for (int mt = 0; mt < 2; mt++) {
                uint32_t off = SWZ64((uint32_t)((wm * 32 + mt * 16 + (lane & 15)) * 64) + chunkb);
                LDSM4(ah[mt], sA + off);
                LDSM4(al[mt], sAl + off);
            }
#pragma unroll
            for (int nt = 0; nt < 4; nt++) {
                uint32_t off = SWZ64((uint32_t)((wn * 64 + nt * 16 + (lane & 15)) * 64) + chunkb);
                uint32_t bh[4], bl[4];
                LDSM4(bh, sB + off);
                LDSM4(bl, sBl + off);
#pragma unroll
                for (int mt = 0; mt < 2; mt++) {
#pragma unroll
                    for (int h2 = 0; h2 < 2; h2++) {
                        const int n8 = nt * 2 + h2;
                        mma16816(cc[mt][n8], ah[mt], bh[h2], bh[h2 + 2]);
                        mma16816(cc[mt][n8], ah[mt], bl[h2], bl[h2 + 2]);
                        mma16816(cc[mt][n8], al[mt], bh[h2], bh[h2 + 2]);
                    }
                }
            }
        }
    }

    // ---- fused epilogue: per-(row, 64-col block) partials, packed float4 ----
    const int nblk = blockIdx.x * 2 + wn;   // 0..15, ascending col order
#pragma unroll
    for (int mt = 0; mt < 2; mt++) {
#pragma unroll
        for (int hf = 0; hf < 2; hf++) {
            const int row = m0 + wm * 32 + mt * 16 + (lane >> 2) + hf * 8;

            float mx = -3.4e38f;
            int am = 0;
#pragma unroll
            for (int n8 = 0; n8 < 8; n8++) {
                const int sc = wn * 64 + n8 * 8 + (lane & 3) * 2;
                const int c = n0 + sc;
                float v0 = cc[mt][n8][hf * 2 + 0] + sbias[sc];
                float v1 = cc[mt][n8][hf * 2 + 1] + sbias[sc + 1];
                if (c < N_COLS && v0 > mx) { mx = v0; am = c; }
                if (c + 1 < N_COLS && v1 > mx) { mx = v1; am = c + 1; }
            }
#pragma unroll
            for (int s = 1; s <= 2; s <<= 1) {
                float om = __shfl_xor_sync(0xffffffffu, mx, s);
                int oa = __shfl_xor_sync(0xffffffffu, am, s);
                if (om > mx || (om == mx && oa < am)) { mx = om; am = oa; }
            }

            float S = 0.f, T = 0.f;
#pragma unroll
            for (int n8 = 0; n8 < 8; n8++) {
                const int sc = wn * 64 + n8 * 8 + (lane & 3) * 2;
                const int c = n0 + sc;
                if (c < N_COLS) {
                    float u = cc[mt][n8][hf * 2 + 0] + sbias[sc] - mx;
                    float e = expf(u); S += e; T += u * e;
                }
                if (c + 1 < N_COLS) {
                    float u = cc[mt][n8][hf * 2 + 1] + sbias[sc + 1] - mx;
                    float e = expf(u); S += e; T += u * e;
                }
            }
#pragma unroll
            for (int s = 1; s <= 2; s <<= 1) {
                S += __shfl_xor_sync(0xffffffffu, S, s);
                T += __shfl_xor_sync(0xffffffffu, T, s);
            }

            if ((lane & 3) == 0) {
                float4 q;
                q.x = mx; q.y = S; q.z = T; q.w = __int_as_float(am);
                g_part[(size_t)row * 16 + nblk] = q;
            }
        }
    }
}

// ---------------------------------------------------------------------------
// Kernel B: fused merge + vote. One block per batch of 64 rows.
//   4 threads/row merge 16 packed partials (coalesced float4 loads),
//   then the block runs the ranking + O(1) tie-augmented count.
// ---------------------------------------------------------------------------
__global__ __launch_bounds__(256)
void vote_kernel(float* __restrict__ out) {
    __shared__ float ent_s[NUM_TTA_];
    __shared__ int votes_s[NUM_TTA_];
    __shared__ int sv[NUM_TTA_];
    __shared__ int counts[N_COLS];

    const int b = blockIdx.x;
    const int tid = threadIdx.x;

    // --- merge phase: row r = tid>>2, partial quarter = tid&3 ---
    {
        const int rl = tid >> 2;
        const int q4 = (tid & 3) * 4;
        const int row = b * NUM_TTA_ + rl;
        float4 p[4];
#pragma unroll
        for (int j = 0; j < 4; j++)
            p[j] = g_part[(size_t)row * 16 + q4 + j];

        // local (m, am): ascending j => ascending col, strict > keeps first
        float m = p[0].x;
        int am = __float_as_int(p[0].w);
#pragma unroll
        for (int j = 1; j < 4; j++) {
            if (p[j].x > m) { m = p[j].x; am = __float_as_int(p[j].w); }
        }
#pragma unroll
        for (int s = 1; s <= 2; s <<= 1) {
            float om = __shfl_xor_sync(0xffffffffu, m, s);
            int oa = __shfl_xor_sync(0xffffffffu, am, s);
            if (om > m || (om == m && oa < am)) { m = om; am = oa; }
        }
        float S = 0.f, T = 0.f;
#pragma unroll
        for (int j = 0; j < 4; j++) {
            float d = p[j].x - m;
            float e = expf(d);
            S += p[j].y * e;
            T += (p[j].z + d * p[j].y) * e;
        }
#pragma unroll
        for (int s = 1; s <= 2; s <<= 1) {
            S += __shfl_xor_sync(0xffffffffu, S, s);
            T += __shfl_xor_sync(0xffffffffu, T, s);
        }
        if ((tid & 3) == 0) {
            ent_s[rl] = logf(S) - T / S;
            votes_s[rl] = am;
        }
    }
    for (int c = tid; c < N_COLS; c += 256) counts[c] = 0;
    __syncthreads();

    // --- ranking phase ---
    if (tid < NUM_TTA_) {
        float e = ent_s[tid];
        int r = 0;
#pragma unroll
        for (int j = 0; j < NUM_TTA_; j++) {
            float ej = ent_s[j];
            r += (ej < e) || (ej == e && j < tid);
        }
        sv[r] = votes_s[tid];
    }
    __syncthreads();

    // --- counting phase ---
    if (tid == 0) {
        for (int i = 0; i < KEPT; i++) counts[sv[i]]++;
        int mx = 0, nmax = 0;
        for (int i = 0; i < KEPT; i++) {
            int c = sv[i];
            bool first = true;
            for (int j = 0; j < i; j++) if (sv[j] == c) { first = false; break; }
            if (first) {
                int cv = counts[c];
                if (cv > mx) { mx = cv; nmax = 1; }
                else if (cv == mx) nmax++;
            }
        }
        for (int i = 0; i < NUM_TTA_ - KEPT; i++) {
            if (nmax > 1) {
                int c = sv[KEPT + i];
                int nc = counts[c] + 1;
                counts[c] = nc;
                if (nc > mx) { mx = nc; nmax = 1; }
                else if (nc == mx) nmax++;
            }
        }
    }
    __syncthreads();

    for (int c = tid; c < N_COLS; c += 256) {
        out[(size_t)b * N_COLS + c] = logf((float)counts[c] * (1.0f / 64.0f) + 1e-8f);
    }
}

// ---------------------------------------------------------------------------
extern "C" void kernel_launch(void* const* d_in, const int* in_sizes, int n_in,
                              void* d_out, int out_size) {
    const float* x = (const float*)d_in[0];
    const float* W = (const float*)d_in[1];
    const float* b = (const float*)d_in[2];
    float* out = (float*)d_out;

    cudaFuncSetAttribute(gemm_fp16x2_kernel,
                         cudaFuncAttributeMaxDynamicSharedMemorySize, SMEM_BYTES);

    split_x_kernel<<<(M_ROWS * (size_t)K_DIM) / 8 / 256, 256>>>(x);
    split_wt_kernel<<<dim3(K_DIM / 32, N_PAD / 32), dim3(32, 32)>>>(W);

    gemm_fp16x2_kernel<<<dim3(N_PAD / BN, M_ROWS / BM), 256, SMEM_BYTES>>>(b);

    vote_kernel<<<NBATCH, 256>>>(out);
}